// round 1
// baseline (speedup 1.0000x reference)
#include <cuda_runtime.h>
#include <cuda_bf16.h>

// AUCM loss: loss = mean over (i in pos, j in neg) of d^2 + MARGIN*relu(d),
// d = 1 - (p_i - n_j). MARGIN = 1.
//
// Strategy: compact positives (~1200 of 16384) into a device-global buffer,
// then a pairwise kernel where grid-x covers negatives and grid-y splits the
// positive list. Positives staged through shared memory; fp32 partials with
// 4-way ILP, fp64 block reduction + one fp64 atomicAdd per block.

#define N_MAX   16384
#define TILE    2048
#define PSPLIT  4
#define THREADS 256
#define MARGIN  1.0f

__device__ float  g_pos[N_MAX];
__device__ int    g_pos_count;
__device__ double g_sum;

__global__ void init_kernel() {
    g_pos_count = 0;
    g_sum = 0.0;
}

__global__ void compact_kernel(const float* __restrict__ preds,
                               const int* __restrict__ targets, int n) {
    int i = blockIdx.x * blockDim.x + threadIdx.x;
    if (i < n && targets[i] == 1) {
        int idx = atomicAdd(&g_pos_count, 1);
        g_pos[idx] = preds[i];
    }
}

__global__ void pairwise_kernel(const float* __restrict__ preds,
                                const int* __restrict__ targets, int n) {
    __shared__ float  s_pos[TILE];
    __shared__ double s_warp[THREADS / 32];

    int i = blockIdx.x * blockDim.x + threadIdx.x;
    bool isNeg = (i < n) && (targets[i] == 0);
    float base = isNeg ? (1.0f + preds[i]) : 0.0f;  // d = base - p_i

    int pcount = g_pos_count;
    int per = (pcount + PSPLIT - 1) / PSPLIT;
    int p0 = blockIdx.y * per;
    int p1 = min(p0 + per, pcount);

    float acc0 = 0.f, acc1 = 0.f, acc2 = 0.f, acc3 = 0.f;

    for (int t = p0; t < p1; t += TILE) {
        int m = min(TILE, p1 - t);
        for (int k = threadIdx.x; k < m; k += blockDim.x)
            s_pos[k] = g_pos[t + k];
        __syncthreads();

        if (isNeg) {
            int k = 0;
            for (; k + 4 <= m; k += 4) {
                float d0 = base - s_pos[k + 0];
                float d1 = base - s_pos[k + 1];
                float d2 = base - s_pos[k + 2];
                float d3 = base - s_pos[k + 3];
                acc0 = fmaf(d0, d0, fmaf(MARGIN, fmaxf(d0, 0.f), acc0));
                acc1 = fmaf(d1, d1, fmaf(MARGIN, fmaxf(d1, 0.f), acc1));
                acc2 = fmaf(d2, d2, fmaf(MARGIN, fmaxf(d2, 0.f), acc2));
                acc3 = fmaf(d3, d3, fmaf(MARGIN, fmaxf(d3, 0.f), acc3));
            }
            for (; k < m; k++) {
                float d = base - s_pos[k];
                acc0 = fmaf(d, d, fmaf(MARGIN, fmaxf(d, 0.f), acc0));
            }
        }
        __syncthreads();
    }

    double acc = (double)((acc0 + acc1) + (acc2 + acc3));
    #pragma unroll
    for (int off = 16; off; off >>= 1)
        acc += __shfl_down_sync(0xffffffffu, acc, off);

    int lane = threadIdx.x & 31, wid = threadIdx.x >> 5;
    if (lane == 0) s_warp[wid] = acc;
    __syncthreads();
    if (wid == 0) {
        double v = (lane < THREADS / 32) ? s_warp[lane] : 0.0;
        #pragma unroll
        for (int off = 4; off; off >>= 1)
            v += __shfl_down_sync(0xffffffffu, v, off);
        if (lane == 0) atomicAdd(&g_sum, v);
    }
}

__global__ void finalize_kernel(float* __restrict__ out, int n, int out_size) {
    int pc = g_pos_count;
    double denom = (double)pc * (double)(n - pc);
    float v = (float)(g_sum / denom);
    for (int i = threadIdx.x; i < out_size; i += blockDim.x) out[i] = v;
}

extern "C" void kernel_launch(void* const* d_in, const int* in_sizes, int n_in,
                              void* d_out, int out_size) {
    const float* preds   = (const float*)d_in[0];
    const int*   targets = (const int*)d_in[1];
    int n = in_sizes[0];

    init_kernel<<<1, 1>>>();
    compact_kernel<<<(n + 255) / 256, 256>>>(preds, targets, n);
    dim3 grid((n + THREADS - 1) / THREADS, PSPLIT);
    pairwise_kernel<<<grid, THREADS>>>(preds, targets, n);
    finalize_kernel<<<1, 32>>>((float*)d_out, n, out_size);
}